// round 2
// baseline (speedup 1.0000x reference)
#include <cuda_runtime.h>

#define HH 512
#define WW 512
#define NB 16
#define PLANE (HH*WW)
#define IMG (3*PLANE)
#define R 7
#define K 15
#define TX 64
#define TY 32
#define RW (TX + 4*R)     // 92  full-res region width (chroma halo)
#define RH (TY + 4*R)     // 60  full-res region height
#define HRW (RW/2)        // 46  half-res region width
#define HRH (RH/2)        // 30  half-res region height
#define DYW (TX + 2*R)    // 78  luma region width
#define DYH (TY + 2*R)    // 46  luma region height
#define HTY (TY/2)        // 16  half-res tile height

__device__ float g_acc[3];

__global__ void zero_acc_kernel() {
    if (threadIdx.x < 3) g_acc[threadIdx.x] = 0.0f;
}

__global__ __launch_bounds__(256) void yuv_loss_kernel(
    const float* __restrict__ inp, const float* __restrict__ tgt)
{
    __shared__ float s_dy[DYH][DYW];   // 46x78 luma diff
    __shared__ float s_du[HRH][HRW];   // 30x46 pooled chroma diff
    __shared__ float s_dv[HRH][HRW];
    __shared__ float s_vy[TY][DYW];    // 32x78 vertical sums (luma)
    __shared__ float s_vu[HTY][HRW];   // 16x46 vertical sums (chroma)
    __shared__ float s_vv[HTY][HRW];
    __shared__ float s_red[3][8];

    const int tid = threadIdx.x;
    const int n   = blockIdx.z;
    const int tx0 = blockIdx.x * TX;
    const int ty0 = blockIdx.y * TY;
    const float* pin = inp + (size_t)n * IMG;
    const float* ptg = tgt + (size_t)n * IMG;

    // ---- Phase 1: diff channels (zero outside image == conv zero-pad) ----
    for (int idx = tid; idx < HRH * HRW; idx += 256) {
        int hr = idx / HRW;
        int hc = idx - hr * HRW;
        int fy = ty0 - 2 * R + 2 * hr;   // even
        int fx = tx0 - 2 * R + 2 * hc;   // even

        float2 ir0 = {0.f,0.f}, ig0 = {0.f,0.f}, ib0 = {0.f,0.f};
        float2 tr0 = {0.f,0.f}, tg0 = {0.f,0.f}, tb0 = {0.f,0.f};
        float2 ir1 = {0.f,0.f}, ig1 = {0.f,0.f}, ib1 = {0.f,0.f};
        float2 tr1 = {0.f,0.f}, tg1 = {0.f,0.f}, tb1 = {0.f,0.f};

        bool cx = (fx >= 0) & (fx < WW);
        if (cx & (fy >= 0) & (fy < HH)) {
            int o = fy * WW + fx;
            ir0 = *(const float2*)(pin + o);
            ig0 = *(const float2*)(pin + PLANE + o);
            ib0 = *(const float2*)(pin + 2*PLANE + o);
            tr0 = *(const float2*)(ptg + o);
            tg0 = *(const float2*)(ptg + PLANE + o);
            tb0 = *(const float2*)(ptg + 2*PLANE + o);
        }
        int fy1 = fy + 1;
        if (cx & (fy1 >= 0) & (fy1 < HH)) {
            int o = fy1 * WW + fx;
            ir1 = *(const float2*)(pin + o);
            ig1 = *(const float2*)(pin + PLANE + o);
            ib1 = *(const float2*)(pin + 2*PLANE + o);
            tr1 = *(const float2*)(ptg + o);
            tg1 = *(const float2*)(ptg + PLANE + o);
            tb1 = *(const float2*)(ptg + 2*PLANE + o);
        }

        float dr00 = ir0.x - tr0.x, dr01 = ir0.y - tr0.y;
        float dr10 = ir1.x - tr1.x, dr11 = ir1.y - tr1.y;
        float dg00 = ig0.x - tg0.x, dg01 = ig0.y - tg0.y;
        float dg10 = ig1.x - tg1.x, dg11 = ig1.y - tg1.y;
        float db00 = ib0.x - tb0.x, db01 = ib0.y - tb0.y;
        float db10 = ib1.x - tb1.x, db11 = ib1.y - tb1.y;

        // pooled chroma diff (the +128 constants cancel in the difference)
        float Dr = dr00 + dr01 + dr10 + dr11;
        float Dg = dg00 + dg01 + dg10 + dg11;
        float Db = db00 + db01 + db10 + db11;
        s_du[hr][hc] = 0.25f * (-0.169f * Dr - 0.331f * Dg + 0.5f  * Db);
        s_dv[hr][hc] = 0.25f * ( 0.5f   * Dr - 0.46f  * Dg - 0.04f * Db);

        // luma diffs for the 46x78 luma halo region
        float dy00 = 0.299f*dr00 + 0.587f*dg00 + 0.114f*db00;
        float dy01 = 0.299f*dr01 + 0.587f*dg01 + 0.114f*db01;
        float dy10 = 0.299f*dr10 + 0.587f*dg10 + 0.114f*db10;
        float dy11 = 0.299f*dr11 + 0.587f*dg11 + 0.114f*db11;

        int dyr = 2 * hr - R;      // region row - 7
        int dyc = 2 * hc - R;
        bool r0ok = (dyr >= 0) & (dyr < DYH);
        bool r1ok = (dyr + 1 >= 0) & (dyr + 1 < DYH);
        bool c0ok = (dyc >= 0) & (dyc < DYW);
        bool c1ok = (dyc + 1 >= 0) & (dyc + 1 < DYW);
        if (r0ok & c0ok) s_dy[dyr][dyc]       = dy00;
        if (r0ok & c1ok) s_dy[dyr][dyc + 1]   = dy01;
        if (r1ok & c0ok) s_dy[dyr + 1][dyc]   = dy10;
        if (r1ok & c1ok) s_dy[dyr + 1][dyc+1] = dy11;
    }
    __syncthreads();

    // ---- Phase 2: vertical 15-tap running sums ----
    if (tid < DYW) {                       // 78 luma columns
        int c = tid;
        float s = 0.f;
        #pragma unroll
        for (int j = 0; j < K; j++) s += s_dy[j][c];
        s_vy[0][c] = s;
        #pragma unroll 4
        for (int r = 1; r < TY; r++) {
            s += s_dy[r + K - 1][c] - s_dy[r - 1][c];
            s_vy[r][c] = s;
        }
    } else if (tid < DYW + 2 * HRW) {      // 2x46 chroma columns
        int t = tid - DYW;
        int ch = t / HRW;
        int c  = t - ch * HRW;
        float (*src)[HRW] = ch ? s_dv : s_du;
        float (*dst)[HRW] = ch ? s_vv : s_vu;
        float s = 0.f;
        #pragma unroll
        for (int j = 0; j < K; j++) s += src[j][c];
        dst[0][c] = s;
        #pragma unroll 5
        for (int r = 1; r < HTY; r++) {
            s += src[r + K - 1][c] - src[r - 1][c];
            dst[r][c] = s;
        }
    }
    __syncthreads();

    // ---- Phase 3: horizontal 15-tap sliding sums, square, accumulate ----
    float accY = 0.f, accU = 0.f, accV = 0.f;
    {   // luma: 32 rows x 8 segments of 8 outputs = 256 threads
        int row = tid >> 3;
        int c0  = (tid & 7) * 8;
        float s = 0.f;
        #pragma unroll
        for (int j = 0; j < K; j++) s += s_vy[row][c0 + j];
        accY = s * s;
        #pragma unroll
        for (int i = 1; i < 8; i++) {
            s += s_vy[row][c0 + i + K - 1] - s_vy[row][c0 + i - 1];
            accY += s * s;
        }
    }
    {   // chroma: 2 ch x 16 rows x 8 segments of 4 outputs = 256 threads
        int ch  = tid >> 7;
        int rem = tid & 127;
        int row = rem >> 3;
        int c0  = (rem & 7) * 4;
        float (*v)[HRW] = ch ? s_vv : s_vu;
        float s = 0.f;
        #pragma unroll
        for (int j = 0; j < K; j++) s += v[row][c0 + j];
        float a = s * s;
        #pragma unroll
        for (int i = 1; i < 4; i++) {
            s += v[row][c0 + i + K - 1] - v[row][c0 + i - 1];
            a += s * s;
        }
        if (ch) accV = a; else accU = a;
    }

    // ---- block reduction ----
    #pragma unroll
    for (int o = 16; o > 0; o >>= 1) {
        accY += __shfl_down_sync(0xffffffffu, accY, o);
        accU += __shfl_down_sync(0xffffffffu, accU, o);
        accV += __shfl_down_sync(0xffffffffu, accV, o);
    }
    int w = tid >> 5, l = tid & 31;
    if (l == 0) { s_red[0][w] = accY; s_red[1][w] = accU; s_red[2][w] = accV; }
    __syncthreads();
    if (tid == 0) {
        float sy = 0.f, su = 0.f, sv = 0.f;
        #pragma unroll
        for (int i = 0; i < 8; i++) { sy += s_red[0][i]; su += s_red[1][i]; sv += s_red[2][i]; }
        atomicAdd(&g_acc[0], sy);
        atomicAdd(&g_acc[1], su);
        atomicAdd(&g_acc[2], sv);
    }
}

__global__ void finalize_kernel(float* out) {
    const float invY = 1.0f / ((float)NB * HH * WW);
    const float invC = 1.0f / ((float)NB * (HH/2) * (WW/2));
    out[0] = g_acc[0] * invY + (g_acc[1] + g_acc[2]) * invC;
}

extern "C" void kernel_launch(void* const* d_in, const int* in_sizes, int n_in,
                              void* d_out, int out_size)
{
    const float* inp = (const float*)d_in[0];
    const float* tgt = (const float*)d_in[1];
    float* out = (float*)d_out;

    zero_acc_kernel<<<1, 32>>>();
    dim3 grid(WW / TX, HH / TY, NB);
    yuv_loss_kernel<<<grid, 256>>>(inp, tgt);
    finalize_kernel<<<1, 1>>>(out);
}

// round 3
// speedup vs baseline: 1.5211x; 1.5211x over previous
#include <cuda_runtime.h>

#define HH 512
#define WW 512
#define NB 16
#define PLANE (HH*WW)
#define IMG (3*PLANE)
#define R 7
#define K 15
#define TX 128
#define TY 64
#define NTHR 512
#define RW (TX + 4*R)      // 156 full-res region width (chroma halo)
#define RH (TY + 4*R)      // 92  full-res region height
#define HRW (RW/2)         // 78  half-res region width
#define HRH (RH/2)         // 46  half-res region height
#define DYW (TX + 2*R)     // 142 luma region width
#define DYH (TY + 2*R)     // 78  luma region height
#define HTY (TY/2)         // 32  half-res tile height
#define GX (WW/TX)         // 4
#define GY (HH/TY)         // 8
#define NBLK (GX*GY*NB)    // 512

// dynamic smem layout (floats)
#define OFF_DY   0
#define OFF_DU   ((DYH+1)*DYW)
#define OFF_DV   (OFF_DU + (HRH+1)*HRW)
#define OFF_RED  (OFF_DV + (HRH+1)*HRW)
#define SM_FLOATS (OFF_RED + 48)
#define SM_BYTES (SM_FLOATS * 4)

__device__ float g_acc[3];          // zero-init at load; reset by last block each call
__device__ unsigned int g_done;

__global__ __launch_bounds__(NTHR) void yuv_loss_kernel(
    const float* __restrict__ inp, const float* __restrict__ tgt,
    float* __restrict__ out)
{
    extern __shared__ float sm[];
    float (*s_dy)[DYW] = (float (*)[DYW])(sm + OFF_DY);  // dy rows i at [i+1]; vy rows r at [r]
    float (*s_du)[HRW] = (float (*)[HRW])(sm + OFF_DU);  // du rows i at [i+1]; vu rows r at [r]
    float (*s_dv)[HRW] = (float (*)[HRW])(sm + OFF_DV);
    float* s_red = sm + OFF_RED;

    const int tid = threadIdx.x;
    const int n   = blockIdx.z;
    const int tx0 = blockIdx.x * TX;
    const int ty0 = blockIdx.y * TY;
    const float* pin = inp + (size_t)n * IMG;
    const float* ptg = tgt + (size_t)n * IMG;

    // ---- Phase 1: diff channels (zero outside image == conv zero-pad) ----
    for (int idx = tid; idx < HRH * HRW; idx += NTHR) {
        int hr = idx / HRW;
        int hc = idx - hr * HRW;
        int fy = ty0 - 2 * R + 2 * hr;   // even
        int fx = tx0 - 2 * R + 2 * hc;   // even -> float2 aligned

        float2 ir0 = {0.f,0.f}, ig0 = {0.f,0.f}, ib0 = {0.f,0.f};
        float2 tr0 = {0.f,0.f}, tg0 = {0.f,0.f}, tb0 = {0.f,0.f};
        float2 ir1 = {0.f,0.f}, ig1 = {0.f,0.f}, ib1 = {0.f,0.f};
        float2 tr1 = {0.f,0.f}, tg1 = {0.f,0.f}, tb1 = {0.f,0.f};

        bool cx = (fx >= 0) & (fx < WW);
        if (cx & (fy >= 0) & (fy < HH)) {
            int o = fy * WW + fx;
            ir0 = *(const float2*)(pin + o);
            ig0 = *(const float2*)(pin + PLANE + o);
            ib0 = *(const float2*)(pin + 2*PLANE + o);
            tr0 = *(const float2*)(ptg + o);
            tg0 = *(const float2*)(ptg + PLANE + o);
            tb0 = *(const float2*)(ptg + 2*PLANE + o);
        }
        int fy1 = fy + 1;
        if (cx & (fy1 >= 0) & (fy1 < HH)) {
            int o = fy1 * WW + fx;
            ir1 = *(const float2*)(pin + o);
            ig1 = *(const float2*)(pin + PLANE + o);
            ib1 = *(const float2*)(pin + 2*PLANE + o);
            tr1 = *(const float2*)(ptg + o);
            tg1 = *(const float2*)(ptg + PLANE + o);
            tb1 = *(const float2*)(ptg + 2*PLANE + o);
        }

        float dr00 = ir0.x - tr0.x, dr01 = ir0.y - tr0.y;
        float dr10 = ir1.x - tr1.x, dr11 = ir1.y - tr1.y;
        float dg00 = ig0.x - tg0.x, dg01 = ig0.y - tg0.y;
        float dg10 = ig1.x - tg1.x, dg11 = ig1.y - tg1.y;
        float db00 = ib0.x - tb0.x, db01 = ib0.y - tb0.y;
        float db10 = ib1.x - tb1.x, db11 = ib1.y - tb1.y;

        // pooled chroma diff (+128 offsets cancel in the difference)
        float Dr = dr00 + dr01 + dr10 + dr11;
        float Dg = dg00 + dg01 + dg10 + dg11;
        float Db = db00 + db01 + db10 + db11;
        s_du[hr + 1][hc] = 0.25f * (-0.169f * Dr - 0.331f * Dg + 0.5f  * Db);
        s_dv[hr + 1][hc] = 0.25f * ( 0.5f   * Dr - 0.46f  * Dg - 0.04f * Db);

        // luma diffs into the 78x142 luma region (stored at row+1)
        float dy00 = 0.299f*dr00 + 0.587f*dg00 + 0.114f*db00;
        float dy01 = 0.299f*dr01 + 0.587f*dg01 + 0.114f*db01;
        float dy10 = 0.299f*dr10 + 0.587f*dg10 + 0.114f*db10;
        float dy11 = 0.299f*dr11 + 0.587f*dg11 + 0.114f*db11;

        int dyr = 2 * hr - R;
        int dyc = 2 * hc - R;
        bool r0ok = (dyr >= 0) & (dyr < DYH);
        bool r1ok = (dyr + 1 >= 0) & (dyr + 1 < DYH);
        bool c0ok = (dyc >= 0) & (dyc < DYW);
        bool c1ok = (dyc + 1 >= 0) & (dyc + 1 < DYW);
        if (r0ok & c0ok) s_dy[dyr + 1][dyc]     = dy00;
        if (r0ok & c1ok) s_dy[dyr + 1][dyc + 1] = dy01;
        if (r1ok & c0ok) s_dy[dyr + 2][dyc]     = dy10;
        if (r1ok & c1ok) s_dy[dyr + 2][dyc + 1] = dy11;
    }
    __syncthreads();

    // ---- Phase 2: vertical 15-tap running sums, written in place over dead rows ----
    // luma: vy[r] = sum dy[r..r+14]; dy[i] lives at s_dy[i+1]; vy[r] -> s_dy[r]
    if (tid < DYW) {
        int c = tid;
        float s = 0.f;
        #pragma unroll
        for (int j = 0; j < K; j++) s += s_dy[j + 1][c];
        s_dy[0][c] = s;
        #pragma unroll 4
        for (int r = 1; r < TY; r++) {
            s += s_dy[r + K][c] - s_dy[r][c];   // + dy[r+14] - dy[r-1]
            s_dy[r][c] = s;                     // vy[r] over dead dy[r-1]
        }
    } else if (tid < DYW + 2 * HRW) {
        int t = tid - DYW;
        int ch = t / HRW;
        int c  = t - ch * HRW;
        float (*b)[HRW] = ch ? s_dv : s_du;
        float s = 0.f;
        #pragma unroll
        for (int j = 0; j < K; j++) s += b[j + 1][c];
        b[0][c] = s;
        #pragma unroll 4
        for (int r = 1; r < HTY; r++) {
            s += b[r + K][c] - b[r][c];
            b[r][c] = s;
        }
    }
    __syncthreads();

    // ---- Phase 3: horizontal 15-tap sliding sums, square, accumulate ----
    float accY = 0.f, accU = 0.f, accV = 0.f;
    {   // luma: 64 rows x 8 segments of 16 outputs = 512 threads
        int row = tid >> 3;
        int c0  = (tid & 7) * 16;
        float s = 0.f;
        #pragma unroll
        for (int j = 0; j < K; j++) s += s_dy[row][c0 + j];
        accY = s * s;
        #pragma unroll
        for (int i = 1; i < 16; i++) {
            s += s_dy[row][c0 + i + K - 1] - s_dy[row][c0 + i - 1];
            accY += s * s;
        }
    }
    {   // chroma: 2 ch x 32 rows x 8 segments of 8 outputs = 512 threads
        int ch  = tid >> 8;
        int rem = tid & 255;
        int row = rem >> 3;
        int c0  = (rem & 7) * 8;
        float (*v)[HRW] = ch ? s_dv : s_du;
        float s = 0.f;
        #pragma unroll
        for (int j = 0; j < K; j++) s += v[row][c0 + j];
        float a = s * s;
        #pragma unroll
        for (int i = 1; i < 8; i++) {
            s += v[row][c0 + i + K - 1] - v[row][c0 + i - 1];
            a += s * s;
        }
        if (ch) accV = a; else accU = a;
    }

    // ---- block reduction (16 warps) ----
    #pragma unroll
    for (int o = 16; o > 0; o >>= 1) {
        accY += __shfl_down_sync(0xffffffffu, accY, o);
        accU += __shfl_down_sync(0xffffffffu, accU, o);
        accV += __shfl_down_sync(0xffffffffu, accV, o);
    }
    int w = tid >> 5, l = tid & 31;
    if (l == 0) { s_red[w] = accY; s_red[16 + w] = accU; s_red[32 + w] = accV; }
    __syncthreads();
    if (tid == 0) {
        float sy = 0.f, su = 0.f, sv = 0.f;
        #pragma unroll
        for (int i = 0; i < 16; i++) { sy += s_red[i]; su += s_red[16+i]; sv += s_red[32+i]; }
        atomicAdd(&g_acc[0], sy);
        atomicAdd(&g_acc[1], su);
        atomicAdd(&g_acc[2], sv);
        __threadfence();
        unsigned int t = atomicAdd(&g_done, 1u);
        if (t == NBLK - 1) {
            const float invY = 1.0f / ((float)NB * HH * WW);
            const float invC = 1.0f / ((float)NB * (HH/2) * (WW/2));
            out[0] = g_acc[0] * invY + (g_acc[1] + g_acc[2]) * invC;
            g_acc[0] = 0.f; g_acc[1] = 0.f; g_acc[2] = 0.f;
            g_done = 0u;
        }
    }
}

extern "C" void kernel_launch(void* const* d_in, const int* in_sizes, int n_in,
                              void* d_out, int out_size)
{
    const float* inp = (const float*)d_in[0];
    const float* tgt = (const float*)d_in[1];
    float* out = (float*)d_out;

    static int configured = 0;
    if (!configured) {
        cudaFuncSetAttribute(yuv_loss_kernel,
                             cudaFuncAttributeMaxDynamicSharedMemorySize, SM_BYTES);
        configured = 1;
    }

    dim3 grid(GX, GY, NB);
    yuv_loss_kernel<<<grid, NTHR, SM_BYTES>>>(inp, tgt, out);
}